// round 6
// baseline (speedup 1.0000x reference)
#include <cuda_runtime.h>
#include <math.h>

// Problem constants (fixed by the dataset)
#define T_TOKENS 16384
#define HID      2880
#define NEXP     128
#define TOPK     4

// Tiling
#define TM       128     // tokens per block
#define BK       16      // k-slice per stage
#define PAD      132     // smem row stride (floats), padded vs 128 to break conflicts
#define NTHREADS 256

#define SMEM_FLOATS (2*BK*PAD + TM*PAD + 2*NEXP)
#define SMEM_BYTES  (SMEM_FLOATS * 4)

__global__ __launch_bounds__(NTHREADS)
void router_kernel(const float* __restrict__ x,
                   const int* __restrict__ mask,      // bool promoted to int32 by harness
                   const float* __restrict__ w,
                   const float* __restrict__ bias,
                   const float* __restrict__ vbias,
                   float* __restrict__ out, int out_size)
{
    extern __shared__ float smem[];
    float* xs = smem;                    // [BK][PAD]  x tile, k-major
    float* ws = xs + BK * PAD;           // [BK][PAD]  w tile, k-major
    float* lg = ws + BK * PAD;           // [TM][PAD]  logits staging
    float* bs = lg + TM * PAD;           // [NEXP] bias
    float* vs = bs + NEXP;               // [NEXP] vision bias

    const int tid  = threadIdx.x;
    const int tok0 = blockIdx.x * TM;

    if (tid < NEXP) { bs[tid] = bias[tid]; vs[tid] = vbias[tid]; }

    const int tx = tid & 15;   // expert group (8 experts)
    const int ty = tid >> 4;   // token group  (8 tokens)

    float acc[8][8];
    #pragma unroll
    for (int i = 0; i < 8; i++)
        #pragma unroll
        for (int j = 0; j < 8; j++) acc[i][j] = 0.f;

    // Global-load slots: slot s = tid + r*256, r in {0,1}
    //   kc = s & 3  -> which float4 within the 16-wide k slice
    //   row = s >> 2 -> token/expert row (0..127)
    float4 xl[2], wl[2];
    #pragma unroll
    for (int r = 0; r < 2; r++) {
        int s = tid + r * NTHREADS;
        int kc = s & 3, row = s >> 2;
        xl[r] = *(const float4*)(x + (size_t)(tok0 + row) * HID + kc * 4);
        wl[r] = *(const float4*)(w + (size_t)row * HID + kc * 4);
    }

    for (int k0 = 0; k0 < HID; k0 += BK) {
        // Store prefetched regs to smem (transposed to k-major)
        #pragma unroll
        for (int r = 0; r < 2; r++) {
            int s = tid + r * NTHREADS;
            int kc = s & 3, row = s >> 2;
            float4 v = xl[r];
            xs[(kc*4+0)*PAD + row] = v.x;
            xs[(kc*4+1)*PAD + row] = v.y;
            xs[(kc*4+2)*PAD + row] = v.z;
            xs[(kc*4+3)*PAD + row] = v.w;
            v = wl[r];
            ws[(kc*4+0)*PAD + row] = v.x;
            ws[(kc*4+1)*PAD + row] = v.y;
            ws[(kc*4+2)*PAD + row] = v.z;
            ws[(kc*4+3)*PAD + row] = v.w;
        }
        __syncthreads();

        // Prefetch next k-slice while computing this one
        int kn = k0 + BK;
        if (kn < HID) {
            #pragma unroll
            for (int r = 0; r < 2; r++) {
                int s = tid + r * NTHREADS;
                int kc = s & 3, row = s >> 2;
                xl[r] = *(const float4*)(x + (size_t)(tok0 + row) * HID + kn + kc * 4);
                wl[r] = *(const float4*)(w + (size_t)row * HID + kn + kc * 4);
            }
        }

        // Compute: 16 k-steps, 8x8 outer product per thread
        #pragma unroll
        for (int kk = 0; kk < BK; kk++) {
            float a[8], b[8];
            float4 t0 = *(const float4*)(xs + kk * PAD + ty * 8);
            float4 t1 = *(const float4*)(xs + kk * PAD + ty * 8 + 4);
            a[0]=t0.x; a[1]=t0.y; a[2]=t0.z; a[3]=t0.w;
            a[4]=t1.x; a[5]=t1.y; a[6]=t1.z; a[7]=t1.w;
            float4 u0 = *(const float4*)(ws + kk * PAD + tx * 8);
            float4 u1 = *(const float4*)(ws + kk * PAD + tx * 8 + 4);
            b[0]=u0.x; b[1]=u0.y; b[2]=u0.z; b[3]=u0.w;
            b[4]=u1.x; b[5]=u1.y; b[6]=u1.z; b[7]=u1.w;
            #pragma unroll
            for (int i = 0; i < 8; i++)
                #pragma unroll
                for (int j = 0; j < 8; j++)
                    acc[i][j] = fmaf(a[i], b[j], acc[i][j]);
        }
        __syncthreads();
    }

    // Stage logits to smem: lg[token][expert]
    #pragma unroll
    for (int i = 0; i < 8; i++)
        #pragma unroll
        for (int j = 0; j < 8; j++)
            lg[(ty*8 + i) * PAD + (tx*8 + j)] = acc[i][j];
    __syncthreads();

    // Cooperatively zero the dense score rows for this block (vectorized)
    {
        float4* srow = (float4*)(out + (size_t)tok0 * NEXP);
        const int n4 = TM * NEXP / 4;
        float4 z = make_float4(0.f, 0.f, 0.f, 0.f);
        for (int i = tid; i < n4; i += NTHREADS) srow[i] = z;
    }
    __syncthreads();

    // Per-token epilogue: bias + (vision bias) + top-4 + softmax + scatter
    const bool write_idx = (out_size >= T_TOKENS * (NEXP + TOPK));
    if (tid < TM) {
        const int t = tid;
        const int tok = tok0 + t;
        const bool vis = (mask[tok] != 0);

        float v0 = -1e30f, v1 = -1e30f, v2 = -1e30f, v3 = -1e30f;
        int   i0 = 0, i1 = 0, i2 = 0, i3 = 0;
        const float* row = lg + (size_t)t * PAD;
        #pragma unroll 4
        for (int e = 0; e < NEXP; e++) {
            float v = row[e] + bs[e] + (vis ? vs[e] : 0.f);
            if (v > v2) {
                if (v > v1) {
                    if (v > v0) { v3=v2;i3=i2; v2=v1;i2=i1; v1=v0;i1=i0; v0=v;i0=e; }
                    else        { v3=v2;i3=i2; v2=v1;i2=i1; v1=v;i1=e; }
                } else          { v3=v2;i3=i2; v2=v;i2=e; }
            } else if (v > v3)  { v3=v;i3=e; }
        }

        // softmax over the 4 selected logits (max-subtracted, matches jax)
        float e1 = expf(v1 - v0);
        float e2 = expf(v2 - v0);
        float e3 = expf(v3 - v0);
        float inv = 1.0f / (1.0f + e1 + e2 + e3);
        float p0 = inv, p1 = e1 * inv, p2 = e2 * inv, p3 = e3 * inv;

        float* orow = out + (size_t)tok * NEXP;
        orow[i0] = p0; orow[i1] = p1; orow[i2] = p2; orow[i3] = p3;

        if (write_idx) {
            float* io = out + (size_t)T_TOKENS * NEXP + (size_t)tok * TOPK;
            io[0] = (float)i0; io[1] = (float)i1; io[2] = (float)i2; io[3] = (float)i3;
        }
    }
}

extern "C" void kernel_launch(void* const* d_in, const int* in_sizes, int n_in,
                              void* d_out, int out_size)
{
    const float* x    = (const float*)d_in[0];
    const int*   mask = (const int*)d_in[1];
    const float* w    = (const float*)d_in[2];
    const float* b    = (const float*)d_in[3];
    const float* vb   = (const float*)d_in[4];
    float* out = (float*)d_out;

    cudaFuncSetAttribute(router_kernel,
                         cudaFuncAttributeMaxDynamicSharedMemorySize, SMEM_BYTES);
    router_kernel<<<T_TOKENS / TM, NTHREADS, SMEM_BYTES>>>(x, mask, w, b, vb, out, out_size);
}

// round 15
// speedup vs baseline: 1.5097x; 1.5097x over previous
#include <cuda_runtime.h>
#include <cuda_bf16.h>
#include <cstdint>
#include <math.h>

// ---------------- problem constants ----------------
#define T_TOKENS 16384
#define HID      2880
#define NEXP     128
#define TOPK     4

#define TM       128              // tokens per CTA
#define BK       64               // fp32 K elements per chunk (=128B bf16 rows)
#define NCHUNK   (HID / BK)       // 45
#define NTHREADS 256
#define TILE_B   16384            // one bf16 tile: 128 rows x 128 bytes (SW128)

// smem: two stage buffers of 6 tiles each (x0,x1,x2,w0,w1,w2), then bias arrays
#define STAGE_B   (6 * TILE_B)            // 98304
#define SM_BIAS   (2 * STAGE_B)           // 196608
#define SM_VBIAS  (SM_BIAS + 512)
#define SMEM_BYTES (SM_VBIAS + 512)       // 197632
#define PADL      132                     // logits row stride (floats)

// pre-split, pre-swizzled weights: [term][chunk][16KB tile]
__device__ unsigned char g_wpre[3 * NCHUNK * TILE_B];

// ---------------- helpers ----------------
__device__ __forceinline__ uint32_t smem_u32(const void* p) {
    uint32_t a;
    asm("{ .reg .u64 t; cvta.to.shared.u64 t, %1; cvt.u32.u64 %0, t; }" : "=r"(a) : "l"(p));
    return a;
}
__device__ __forceinline__ uint32_t swz128(uint32_t off) { return off ^ ((off >> 3) & 0x70); }

__device__ __forceinline__ uint32_t packbf(float lo, float hi) {
    uint32_t r;  // hi -> upper half, lo -> lower half
    asm("cvt.rn.bf16x2.f32 %0, %1, %2;" : "=r"(r) : "f"(hi), "f"(lo));
    return r;
}

__device__ __forceinline__ void ldsm_x4(uint32_t* r, uint32_t addr) {
    asm volatile("ldmatrix.sync.aligned.m8n8.x4.shared.b16 {%0,%1,%2,%3}, [%4];"
                 : "=r"(r[0]), "=r"(r[1]), "=r"(r[2]), "=r"(r[3]) : "r"(addr));
}

// in-place accumulate: C += A*B
__device__ __forceinline__ void mma_bf16(float* c, const uint32_t* a, const uint32_t* b) {
    asm volatile("mma.sync.aligned.m16n8k16.row.col.f32.bf16.bf16.f32 "
                 "{%0,%1,%2,%3}, {%4,%5,%6,%7}, {%8,%9}, {%0,%1,%2,%3};"
                 : "+f"(c[0]), "+f"(c[1]), "+f"(c[2]), "+f"(c[3])
                 : "r"(a[0]), "r"(a[1]), "r"(a[2]), "r"(a[3]), "r"(b[0]), "r"(b[1]));
}
// fresh-start: D = A*B + 0 (zeroes the chunk-local temp without MOVs)
__device__ __forceinline__ void mma_bf16_init(float* d, const uint32_t* a, const uint32_t* b) {
    asm volatile("mma.sync.aligned.m16n8k16.row.col.f32.bf16.bf16.f32 "
                 "{%0,%1,%2,%3}, {%4,%5,%6,%7}, {%8,%9}, {%10,%11,%12,%13};"
                 : "=f"(d[0]), "=f"(d[1]), "=f"(d[2]), "=f"(d[3])
                 : "r"(a[0]), "r"(a[1]), "r"(a[2]), "r"(a[3]), "r"(b[0]), "r"(b[1]),
                   "f"(0.f), "f"(0.f), "f"(0.f), "f"(0.f));
}

#define CP_ASYNC16(saddr, gptr) \
    asm volatile("cp.async.cg.shared.global [%0], [%1], 16;" :: "r"(saddr), "l"(gptr))
#define CP_COMMIT() asm volatile("cp.async.commit_group;" ::: "memory")
#define CP_WAIT0()  asm volatile("cp.async.wait_group 0;" ::: "memory")

// ---------------- pre-kernel: split + swizzle w ----------------
__global__ void wsplit_kernel(const float* __restrict__ w) {
    const int c = blockIdx.x;            // k-chunk
    for (int s = threadIdx.x; s < 128 * 32; s += blockDim.x) {
        const int row = s >> 5;          // expert
        const int pr  = s & 31;          // pair of k elems
        const float* p = w + (size_t)row * HID + c * BK + pr * 2;
        float a0 = p[0], a1 = p[1];
        uint32_t h0 = packbf(a0, a1);
        float g0 = __uint_as_float(h0 << 16), g1 = __uint_as_float(h0 & 0xFFFF0000u);
        float r0 = a0 - g0, r1 = a1 - g1;
        uint32_t h1 = packbf(r0, r1);
        float q0 = __uint_as_float(h1 << 16), q1 = __uint_as_float(h1 & 0xFFFF0000u);
        uint32_t h2 = packbf(r0 - q0, r1 - q1);
        uint32_t sw = swz128(row * 128 + pr * 4);
        *(uint32_t*)(g_wpre + (size_t)(0 * NCHUNK + c) * TILE_B + sw) = h0;
        *(uint32_t*)(g_wpre + (size_t)(1 * NCHUNK + c) * TILE_B + sw) = h1;
        *(uint32_t*)(g_wpre + (size_t)(2 * NCHUNK + c) * TILE_B + sw) = h2;
    }
}

// ---------------- main kernel ----------------
__global__ __launch_bounds__(NTHREADS, 1)
void router_mma_kernel(const float* __restrict__ x,
                       const int* __restrict__ mask,
                       const float* __restrict__ bias,
                       const float* __restrict__ vbias,
                       float* __restrict__ out, int out_size)
{
    extern __shared__ char smem[];
    const uint32_t sb = smem_u32(smem);
    const int tid  = threadIdx.x;
    const int wid  = tid >> 5;
    const int lane = tid & 31;
    const int tok0 = blockIdx.x * TM;

    float* bs = (float*)(smem + SM_BIAS);
    float* vs = (float*)(smem + SM_VBIAS);
    if (tid < NEXP) { bs[tid] = bias[tid]; vs[tid] = vbias[tid]; }

    // warp tile: 64 tokens x 32 experts
    const int m0 = (wid & 1) * 64;
    const int n0 = (wid >> 1) * 32;

    // ldmatrix A lane mapping (m16n8k16 frag order M0..M3)
    const int lm_row = (lane & 7) + ((lane >> 3) & 1) * 8;  // 0..15
    const int lm_k16 = (lane >> 4) * 16;                     // byte 0 or 16
    // B lds lane mapping
    const int b_n  = lane >> 2;        // 0..7
    const int b_kb = (lane & 3) * 4;   // byte within 16

    float acc[4][4][4];   // main (two-level) accumulator
    #pragma unroll
    for (int i = 0; i < 4; i++)
        #pragma unroll
        for (int j = 0; j < 4; j++)
            #pragma unroll
            for (int q = 0; q < 4; q++) acc[i][j][q] = 0.f;

    // producer slot: 2 threads per token row, 32 consecutive k each
    const int prow  = tid >> 1;
    const int phalf = tid & 1;
    const float* xrow = x + (size_t)(tok0 + prow) * HID + phalf * 32;

    float4 xr[8];

    auto load_x = [&](int ch) {
        const float* src = xrow + ch * BK;
        #pragma unroll
        for (int i = 0; i < 8; i++) xr[i] = *(const float4*)(src + i * 4);
    };
    auto cpasync_w = [&](int ch, uint32_t sbase) {
        #pragma unroll
        for (int j = 0; j < 12; j++) {
            int u = tid + j * NTHREADS;       // 0..3071
            int t = u >> 10;                  // tile 0..2
            int off = (u & 1023) * 16;
            const char* src = (const char*)g_wpre + (size_t)(t * NCHUNK + ch) * TILE_B + off;
            CP_ASYNC16(sbase + (3 + t) * TILE_B + off, src);
        }
        CP_COMMIT();
    };
    auto convert_store = [&](uint32_t sbase) {
        float vv[16], vv2[16];
        float* vp = vv;
        #pragma unroll
        for (int i = 0; i < 4; i++) {
            vp[0] = xr[i].x; vp[1] = xr[i].y; vp[2] = xr[i].z; vp[3] = xr[i].w; vp += 4;
        }
        float* vq = vv2;
        #pragma unroll
        for (int i = 4; i < 8; i++) {
            vq[0] = xr[i].x; vq[1] = xr[i].y; vq[2] = xr[i].z; vq[3] = xr[i].w; vq += 4;
        }
        #pragma unroll
        for (int pr = 0; pr < 16; pr++) {
            float a0 = (pr < 8) ? vv[2*pr]   : vv2[2*(pr-8)];
            float a1 = (pr < 8) ? vv[2*pr+1] : vv2[2*(pr-8)+1];
            uint32_t h0 = packbf(a0, a1);
            float g0 = __uint_as_float(h0 << 16), g1 = __uint_as_float(h0 & 0xFFFF0000u);
            float r0 = a0 - g0, r1 = a1 - g1;
            uint32_t h1 = packbf(r0, r1);
            float q0 = __uint_as_float(h1 << 16), q1 = __uint_as_float(h1 & 0xFFFF0000u);
            uint32_t h2 = packbf(r0 - q0, r1 - q1);
            uint32_t sw = swz128((uint32_t)(prow * 128 + phalf * 64 + pr * 4));
            *(uint32_t*)(smem + sbase - sb + 0 * TILE_B + sw) = h0;
            *(uint32_t*)(smem + sbase - sb + 1 * TILE_B + sw) = h1;
            *(uint32_t*)(smem + sbase - sb + 2 * TILE_B + sw) = h2;
        }
    };

    // ---- prologue: chunk 0 ----
    load_x(0);
    cpasync_w(0, sb + 0);
    convert_store(sb + 0);
    CP_WAIT0();
    __syncthreads();

    // ---- mainloop ----
    for (int ch = 0; ch < NCHUNK; ch++) {
        const uint32_t cur = sb + (uint32_t)(ch & 1) * STAGE_B;
        const int nxt = ch + 1;
        const uint32_t nbuf = sb + (uint32_t)(nxt & 1) * STAGE_B;

        if (nxt < NCHUNK) {
            cpasync_w(nxt, nbuf);
            load_x(nxt);
        }

        // chunk-local temp accumulator (first mma per tile initializes it)
        float tmp[4][4][4];

        #pragma unroll
        for (int kt = 0; kt < 4; kt++) {
            uint32_t aoff[4], boff[4][2];
            #pragma unroll
            for (int mt = 0; mt < 4; mt++)
                aoff[mt] = swz128((uint32_t)((m0 + mt * 16 + lm_row) * 128 + kt * 32 + lm_k16));
            #pragma unroll
            for (int nt = 0; nt < 4; nt++) {
                uint32_t base = (uint32_t)((n0 + nt * 8 + b_n) * 128 + kt * 32 + b_kb);
                boff[nt][0] = swz128(base);
                boff[nt][1] = swz128(base + 16);
            }
            #pragma unroll
            for (int xc = 0; xc < 3; xc++) {
                const uint32_t abase = cur + xc * TILE_B;
                uint32_t a[4][4];
                #pragma unroll
                for (int mt = 0; mt < 4; mt++) ldsm_x4(a[mt], abase + aoff[mt]);
                const int nw = 3 - xc;
                #pragma unroll
                for (int wc = 0; wc < 3; wc++) {
                    if (wc >= nw) break;
                    const char* wb = smem + (cur - sb) + (3 + wc) * TILE_B;
                    uint32_t b[4][2];
                    #pragma unroll
                    for (int nt = 0; nt < 4; nt++) {
                        b[nt][0] = *(const uint32_t*)(wb + boff[nt][0]);
                        b[nt][1] = *(const uint32_t*)(wb + boff[nt][1]);
                    }
                    #pragma unroll
                    for (int mt = 0; mt < 4; mt++)
                        #pragma unroll
                        for (int nt = 0; nt < 4; nt++) {
                            if (kt == 0 && xc == 0 && wc == 0)
                                mma_bf16_init(tmp[mt][nt], a[mt], b[nt]);
                            else
                                mma_bf16(tmp[mt][nt], a[mt], b[nt]);
                        }
                }
            }
        }

        // fold chunk partial into main accumulator (two-level summation)
        #pragma unroll
        for (int mt = 0; mt < 4; mt++)
            #pragma unroll
            for (int nt = 0; nt < 4; nt++)
                #pragma unroll
                for (int q = 0; q < 4; q++)
                    acc[mt][nt][q] += tmp[mt][nt][q];

        if (nxt < NCHUNK) {
            convert_store(nbuf);
            CP_WAIT0();
        }
        __syncthreads();
    }

    // ---- epilogue ----
    float* lg = (float*)smem;
    {
        const int r0 = m0 + (lane >> 2);
        const int c0 = n0 + (lane & 3) * 2;
        #pragma unroll
        for (int mt = 0; mt < 4; mt++)
            #pragma unroll
            for (int nt = 0; nt < 4; nt++) {
                const int r = r0 + mt * 16;
                const int c = c0 + nt * 8;
                lg[r * PADL + c]           = acc[mt][nt][0];
                lg[r * PADL + c + 1]       = acc[mt][nt][1];
                lg[(r + 8) * PADL + c]     = acc[mt][nt][2];
                lg[(r + 8) * PADL + c + 1] = acc[mt][nt][3];
            }
    }

    // zero this block's dense score rows
    {
        float4* orow = (float4*)(out + (size_t)tok0 * NEXP);
        float4 z = make_float4(0.f, 0.f, 0.f, 0.f);
        #pragma unroll
        for (int i = 0; i < (TM * NEXP / 4) / NTHREADS; i++)
            orow[tid + i * NTHREADS] = z;
    }
    __syncthreads();

    const bool write_idx = (out_size >= T_TOKENS * (NEXP + TOPK));
    if (tid < TM) {
        const int tok = tok0 + tid;
        const bool vis = (mask[tok] != 0);
        const float* row = lg + (size_t)tid * PADL;

        float v0 = -1e30f, v1 = -1e30f, v2 = -1e30f, v3 = -1e30f;
        int   i0 = 0, i1 = 0, i2 = 0, i3 = 0;
        #pragma unroll 4
        for (int e = 0; e < NEXP; e++) {
            float v = row[e] + bs[e] + (vis ? vs[e] : 0.f);
            if (v > v2) {
                if (v > v1) {
                    if (v > v0) { v3=v2;i3=i2; v2=v1;i2=i1; v1=v0;i1=i0; v0=v;i0=e; }
                    else        { v3=v2;i3=i2; v2=v1;i2=i1; v1=v;i1=e; }
                } else          { v3=v2;i3=i2; v2=v;i2=e; }
            } else if (v > v3)  { v3=v;i3=e; }
        }

        float e1 = expf(v1 - v0);
        float e2 = expf(v2 - v0);
        float e3 = expf(v3 - v0);
        float inv = 1.0f / (1.0f + e1 + e2 + e3);

        float* orow = out + (size_t)tok * NEXP;
        orow[i0] = inv; orow[i1] = e1 * inv; orow[i2] = e2 * inv; orow[i3] = e3 * inv;

        if (write_idx) {
            float* io = out + (size_t)T_TOKENS * NEXP + (size_t)tok * TOPK;
            io[0] = (float)i0; io[1] = (float)i1; io[2] = (float)i2; io[3] = (float)i3;
        }
    }
}

// ---------------- launch ----------------
extern "C" void kernel_launch(void* const* d_in, const int* in_sizes, int n_in,
                              void* d_out, int out_size)
{
    const float* x    = (const float*)d_in[0];
    const int*   mask = (const int*)d_in[1];
    const float* w    = (const float*)d_in[2];
    const float* b    = (const float*)d_in[3];
    const float* vb   = (const float*)d_in[4];
    float* out = (float*)d_out;

    wsplit_kernel<<<NCHUNK, 256>>>(w);

    cudaFuncSetAttribute(router_mma_kernel,
                         cudaFuncAttributeMaxDynamicSharedMemorySize, SMEM_BYTES);
    router_mma_kernel<<<T_TOKENS / TM, NTHREADS, SMEM_BYTES>>>(x, mask, b, vb, out, out_size);
}